// round 1
// baseline (speedup 1.0000x reference)
#include <cuda_runtime.h>

// Problem constants
#define BDIM 2
#define VDIM 8
#define PDIM 4096
#define DDIM 1024
#define NREF 256
#define EN   16384        // 4 extra frames * 4096
#define NTOPK 4

// Scratch (device globals: allocation-free)
__device__ float g_sim[BDIM * NREF * EN];        // 33.5 MB
__device__ float g_inv_norm[BDIM * EN];
__device__ int   g_topk[BDIM * NREF * NTOPK];
__device__ float g_accum[3];

__constant__ int c_ST[3] = {2, 4, 6};   // SHARED_TEACHER
__constant__ int c_SS[3] = {1, 2, 3};   // SHARED_STUDENT

// ---------------------------------------------------------------------------
// K1: inverse norms of extra_t rows (and zero the accumulators)
// ---------------------------------------------------------------------------
__global__ void k_norm(const float* __restrict__ teacher) {
    int be = blockIdx.x;                 // [0, B*EN)
    int b = be >> 14;
    int e = be & (EN - 1);
    int v = 2 * (e >> 12) + 1;           // EXTRA_FRAMES = {1,3,5,7}
    int p = e & (PDIM - 1);
    const float* row = teacher + ((size_t)(b * VDIM + v) * PDIM + p) * DDIM;

    float4 x = ((const float4*)row)[threadIdx.x];   // 256 threads * 4 = 1024
    float ss = x.x * x.x + x.y * x.y + x.z * x.z + x.w * x.w;
    #pragma unroll
    for (int o = 16; o; o >>= 1) ss += __shfl_xor_sync(0xffffffffu, ss, o);

    __shared__ float sh[8];
    if ((threadIdx.x & 31) == 0) sh[threadIdx.x >> 5] = ss;
    __syncthreads();
    if (threadIdx.x == 0) {
        float t = 0.f;
        #pragma unroll
        for (int i = 0; i < 8; i++) t += sh[i];
        g_inv_norm[be] = 1.0f / fmaxf(sqrtf(t), 1e-12f);
    }
    if (be == 0 && threadIdx.x < 3) g_accum[threadIdx.x] = 0.f;
}

// ---------------------------------------------------------------------------
// K2: sim GEMM.  C[r,e] = dot(ref_t[r], extra_t[e]) * inv_norm[e]
// 128x128x16 tiles, 256 threads, 8x8 per thread, k-major smem.
// ---------------------------------------------------------------------------
#define BM 128
#define BN 128
#define BK 16
#define SMP (BM + 4)   // padded row length (132 floats, 16B-aligned rows)

__global__ void __launch_bounds__(256, 2)
k_gemm(const float* __restrict__ teacher, const int* __restrict__ ref_perm) {
    __shared__ float As[BK][SMP];
    __shared__ float Bs[BK][SMP];

    const int b     = blockIdx.z;
    const int rbase = blockIdx.y * BM;
    const int ebase = blockIdx.x * BN;
    const int tid   = threadIdx.x;
    const int tx    = tid & 15;
    const int ty    = tid >> 4;

    const int lrow = tid >> 2;          // 0..63
    const int kq   = tid & 3;
    const int k0   = kq * 4;

    const int v     = 2 * (ebase >> 12) + 1;
    const int pbase = ebase & (PDIM - 1);

    const float* a_ptr0 = teacher + ((size_t)(b * VDIM) * PDIM + ref_perm[rbase + lrow])      * DDIM + k0;
    const float* a_ptr1 = teacher + ((size_t)(b * VDIM) * PDIM + ref_perm[rbase + lrow + 64]) * DDIM + k0;
    const float* b_ptr0 = teacher + ((size_t)(b * VDIM + v) * PDIM + pbase + lrow)      * DDIM + k0;
    const float* b_ptr1 = teacher + ((size_t)(b * VDIM + v) * PDIM + pbase + lrow + 64) * DDIM + k0;

    float acc[8][8];
    #pragma unroll
    for (int i = 0; i < 8; i++)
        #pragma unroll
        for (int j = 0; j < 8; j++) acc[i][j] = 0.f;

    float4 pa0 = *(const float4*)(a_ptr0);
    float4 pa1 = *(const float4*)(a_ptr1);
    float4 pb0 = *(const float4*)(b_ptr0);
    float4 pb1 = *(const float4*)(b_ptr1);

    for (int kt = 0; kt < DDIM; kt += BK) {
        // transpose-store current tile into k-major smem
        As[k0 + 0][lrow] = pa0.x; As[k0 + 1][lrow] = pa0.y;
        As[k0 + 2][lrow] = pa0.z; As[k0 + 3][lrow] = pa0.w;
        As[k0 + 0][lrow + 64] = pa1.x; As[k0 + 1][lrow + 64] = pa1.y;
        As[k0 + 2][lrow + 64] = pa1.z; As[k0 + 3][lrow + 64] = pa1.w;
        Bs[k0 + 0][lrow] = pb0.x; Bs[k0 + 1][lrow] = pb0.y;
        Bs[k0 + 2][lrow] = pb0.z; Bs[k0 + 3][lrow] = pb0.w;
        Bs[k0 + 0][lrow + 64] = pb1.x; Bs[k0 + 1][lrow + 64] = pb1.y;
        Bs[k0 + 2][lrow + 64] = pb1.z; Bs[k0 + 3][lrow + 64] = pb1.w;
        __syncthreads();

        if (kt + BK < DDIM) {        // prefetch next tile into registers
            pa0 = *(const float4*)(a_ptr0 + kt + BK);
            pa1 = *(const float4*)(a_ptr1 + kt + BK);
            pb0 = *(const float4*)(b_ptr0 + kt + BK);
            pb1 = *(const float4*)(b_ptr1 + kt + BK);
        }

        #pragma unroll
        for (int kk = 0; kk < BK; kk++) {
            float a[8], bb[8];
            *(float4*)(a)      = *(const float4*)&As[kk][ty * 4];
            *(float4*)(a + 4)  = *(const float4*)&As[kk][64 + ty * 4];
            *(float4*)(bb)     = *(const float4*)&Bs[kk][tx * 4];
            *(float4*)(bb + 4) = *(const float4*)&Bs[kk][64 + tx * 4];
            #pragma unroll
            for (int i = 0; i < 8; i++)
                #pragma unroll
                for (int j = 0; j < 8; j++) acc[i][j] += a[i] * bb[j];
        }
        __syncthreads();
    }

    // epilogue: scale by inv_norm[e], write sim
    const float* invp = g_inv_norm + b * EN + ebase;
    float4 iv0 = *(const float4*)(invp + tx * 4);
    float4 iv1 = *(const float4*)(invp + 64 + tx * 4);

    #pragma unroll
    for (int u = 0; u < 8; u++) {
        int R = rbase + (u >> 2) * 64 + ty * 4 + (u & 3);
        float* orow = g_sim + ((size_t)(b * NREF + R)) * EN + ebase;
        float4 o0, o1;
        o0.x = acc[u][0] * iv0.x; o0.y = acc[u][1] * iv0.y;
        o0.z = acc[u][2] * iv0.z; o0.w = acc[u][3] * iv0.w;
        o1.x = acc[u][4] * iv1.x; o1.y = acc[u][5] * iv1.y;
        o1.z = acc[u][6] * iv1.z; o1.w = acc[u][7] * iv1.w;
        *(float4*)(orow + tx * 4)      = o0;
        *(float4*)(orow + 64 + tx * 4) = o1;
    }
}

// ---------------------------------------------------------------------------
// K3: top-4 indices per (b, r)
// ---------------------------------------------------------------------------
__device__ __forceinline__ void ins4(float x, int e, float* v, int* id) {
    if (x <= v[3]) return;
    v[3] = x; id[3] = e;
    #pragma unroll
    for (int j = 3; j >= 1; j--) {
        if (v[j] > v[j - 1]) {
            float tv = v[j]; v[j] = v[j - 1]; v[j - 1] = tv;
            int ti = id[j]; id[j] = id[j - 1]; id[j - 1] = ti;
        }
    }
}

__global__ void k_topk() {
    int r = blockIdx.x, b = blockIdx.y;
    const float* row = g_sim + ((size_t)(b * NREF + r)) * EN;
    int tid = threadIdx.x;

    float v[4] = {-3.4e38f, -3.4e38f, -3.4e38f, -3.4e38f};
    int id[4] = {0, 0, 0, 0};
    for (int e = tid; e < EN; e += 256) ins4(row[e], e, v, id);

    __shared__ float sv[1024];
    __shared__ int   si[1024];
    #pragma unroll
    for (int j = 0; j < 4; j++) { sv[tid * 4 + j] = v[j]; si[tid * 4 + j] = id[j]; }
    __syncthreads();

    float v2[4] = {-3.4e38f, -3.4e38f, -3.4e38f, -3.4e38f};
    int id2[4] = {0, 0, 0, 0};
    if (tid < 32) {
        for (int t = tid * 32; t < tid * 32 + 32; t++) ins4(sv[t], si[t], v2, id2);
    }
    __syncthreads();
    if (tid < 32) {
        #pragma unroll
        for (int j = 0; j < 4; j++) { sv[tid * 4 + j] = v2[j]; si[tid * 4 + j] = id2[j]; }
    }
    __syncthreads();
    if (tid == 0) {
        float v3[4] = {-3.4e38f, -3.4e38f, -3.4e38f, -3.4e38f};
        int id3[4] = {0, 0, 0, 0};
        for (int t = 0; t < 128; t++) ins4(sv[t], si[t], v3, id3);
        #pragma unroll
        for (int j = 0; j < 4; j++) g_topk[(b * NREF + r) * 4 + j] = id3[j];
    }
}

// ---------------------------------------------------------------------------
// K4: KL + smooth-L1 losses. One warp per KL row-pair.
//   warps [0,1536):      d1   (3 iters x B x 256)
//   warps [1536,3584):   d2   (B x 256 x 4)  -- computed once (identical per iter)
//   warps [3584,9728):   d3   (3 iters x B x 256 x 4)
// ---------------------------------------------------------------------------
__global__ void __launch_bounds__(256)
k_loss(const float* __restrict__ teacher, const float* __restrict__ student,
       const int* __restrict__ ref_perm, const int* __restrict__ shared_perm) {
    __shared__ float sacc[3];
    int tid = threadIdx.x;
    if (tid < 3) sacc[tid] = 0.f;
    __syncthreads();

    int w = blockIdx.x * 8 + (tid >> 5);
    int lane = tid & 31;

    const float *pa, *pb, *pc, *pd;
    int target;
    if (w < 1536) {
        target = 0;
        int i = w / 512, rem = w & 511;
        int b = rem >> 8, r = rem & 255;
        int rp = ref_perm[r], sp = shared_perm[r];
        pa = teacher + ((size_t)(b * VDIM) * PDIM + rp) * DDIM;
        pb = teacher + ((size_t)(b * VDIM + c_ST[i]) * PDIM + sp) * DDIM;
        pc = student + ((size_t)(b * 4) * PDIM + rp) * DDIM;
        pd = student + ((size_t)(b * 4 + c_SS[i]) * PDIM + sp) * DDIM;
    } else if (w < 3584) {
        target = 1;
        int t = w - 1536;
        int b = t >> 10, rem = t & 1023;
        int r = rem >> 2, k = rem & 3;
        int rp = ref_perm[r];
        int e = g_topk[((b << 8) + r) * 4 + k];
        int v = 2 * (e >> 12) + 1, p = e & (PDIM - 1);
        pa = teacher + ((size_t)(b * VDIM) * PDIM + rp) * DDIM;
        pc = student + ((size_t)(b * 4) * PDIM + rp) * DDIM;
        pb = pd = teacher + ((size_t)(b * VDIM + v) * PDIM + p) * DDIM;
    } else {
        target = 2;
        int t = w - 3584;
        int i = t >> 11, rem = t & 2047;
        int b = rem >> 10, r = (rem >> 2) & 255, k = rem & 3;
        int sp = shared_perm[r];
        int e = g_topk[((b << 8) + r) * 4 + k];
        int v = 2 * (e >> 12) + 1, p = e & (PDIM - 1);
        pa = teacher + ((size_t)(b * VDIM + c_ST[i]) * PDIM + sp) * DDIM;
        pc = student + ((size_t)(b * 4 + c_SS[i]) * PDIM + sp) * DDIM;
        pb = pd = teacher + ((size_t)(b * VDIM + v) * PDIM + p) * DDIM;
    }

    float dt[32], ds[32];
    bool same = (pb == pd);
    #pragma unroll
    for (int j = 0; j < 8; j++) {
        int idx = lane * 4 + j * 128;
        float4 A  = *(const float4*)(pa + idx);
        float4 Bv = *(const float4*)(pb + idx);
        float4 C  = *(const float4*)(pc + idx);
        float4 Dv = same ? Bv : *(const float4*)(pd + idx);
        dt[4 * j + 0] = A.x - Bv.x; dt[4 * j + 1] = A.y - Bv.y;
        dt[4 * j + 2] = A.z - Bv.z; dt[4 * j + 3] = A.w - Bv.w;
        ds[4 * j + 0] = C.x - Dv.x; ds[4 * j + 1] = C.y - Dv.y;
        ds[4 * j + 2] = C.z - Dv.z; ds[4 * j + 3] = C.w - Dv.w;
    }

    float mt = -3.4e38f, ms = -3.4e38f;
    #pragma unroll
    for (int i = 0; i < 32; i++) { mt = fmaxf(mt, dt[i]); ms = fmaxf(ms, ds[i]); }
    #pragma unroll
    for (int o = 16; o; o >>= 1) {
        mt = fmaxf(mt, __shfl_xor_sync(0xffffffffu, mt, o));
        ms = fmaxf(ms, __shfl_xor_sync(0xffffffffu, ms, o));
    }
    float st = 0.f, ssum = 0.f;
    #pragma unroll
    for (int i = 0; i < 32; i++) { st += expf(dt[i] - mt); ssum += expf(ds[i] - ms); }
    #pragma unroll
    for (int o = 16; o; o >>= 1) {
        st   += __shfl_xor_sync(0xffffffffu, st, o);
        ssum += __shfl_xor_sync(0xffffffffu, ssum, o);
    }
    float lset = mt + logf(st);
    float lses = ms + logf(ssum);

    float acc = 0.f;
    #pragma unroll
    for (int i = 0; i < 32; i++) acc += expf(dt[i] - lset) * (dt[i] - ds[i]);
    #pragma unroll
    for (int o = 16; o; o >>= 1) acc += __shfl_xor_sync(0xffffffffu, acc, o);

    if (lane == 0) {
        float kl = acc - lset + lses;
        float ax = fabsf(kl);
        float sl = (ax < 0.5f) ? kl * kl : (ax - 0.25f);   // smooth_l1, beta=0.5
        atomicAdd(&sacc[target], sl);
    }
    __syncthreads();
    if (tid < 3) atomicAdd(&g_accum[tid], sacc[tid]);
}

// ---------------------------------------------------------------------------
// K5: final combine
//   loss = sum_d1/1536 + sum_d2/2048 + sum_d3/6144
//   (d2 computed once; reference's 3x repetition cancels: 3*s2 / (3*2048))
// ---------------------------------------------------------------------------
__global__ void k_final(float* __restrict__ out) {
    out[0] = g_accum[0] * (1.0f / 1536.0f)
           + g_accum[1] * (1.0f / 2048.0f)
           + g_accum[2] * (1.0f / 6144.0f);
}

// ---------------------------------------------------------------------------
extern "C" void kernel_launch(void* const* d_in, const int* in_sizes, int n_in,
                              void* d_out, int out_size) {
    const float* teacher     = (const float*)d_in[0];
    const float* student     = (const float*)d_in[1];
    const int*   ref_perm    = (const int*)d_in[2];
    const int*   shared_perm = (const int*)d_in[3];
    float* out = (float*)d_out;

    k_norm<<<BDIM * EN, 256>>>(teacher);
    k_gemm<<<dim3(EN / BN, NREF / BM, BDIM), 256>>>(teacher, ref_perm);
    k_topk<<<dim3(NREF, BDIM), 256>>>();
    k_loss<<<9728 / 8, 256>>>(teacher, student, ref_perm, shared_perm);
    k_final<<<1, 1>>>(out);
}

// round 2
// speedup vs baseline: 2.3967x; 2.3967x over previous
#include <cuda_runtime.h>
#include <cuda_bf16.h>
#include <cstdint>

// Problem constants
#define BDIM 2
#define VDIM 8
#define PDIM 4096
#define DDIM 1024
#define NREF 256
#define EN   16384        // 4 extra frames * 4096
#define NCAND 8

// Scratch (device globals: allocation-free)
__device__ float g_sim[BDIM * NREF * EN];        // 33.5 MB
__device__ int   g_cand[BDIM * NREF * NCAND];
__device__ int   g_topk[BDIM * NREF * 4];
__device__ float g_accum[3];

__constant__ int c_ST[3] = {2, 4, 6};   // SHARED_TEACHER
__constant__ int c_SS[3] = {1, 2, 3};   // SHARED_STUDENT

// ---------------------------------------------------------------------------
// K1: sim GEMM on tensor cores (bf16 in, fp32 accum), fused f32->bf16 convert
//     and fused B-row norm.  C[r,e] = dot(ref_t[r], extra_t[e]) / ||extra_t[e]||
// 128x128 block tile, BK=32, 8 warps (2x4), warp tile 64x32, mma.m16n8k16.
// ---------------------------------------------------------------------------
#define GBM 128
#define GBN 128
#define GBK 32
#define SROW 40   // halves per smem row (32 data + 8 pad); 80B, 16B-aligned

__global__ void __launch_bounds__(256, 1)
k_gemm(const float* __restrict__ teacher, const int* __restrict__ ref_perm) {
    __shared__ __align__(16) __nv_bfloat16 As[GBM][SROW];
    __shared__ __align__(16) __nv_bfloat16 Bs[GBN][SROW];
    __shared__ float s_inv[GBN];

    const int b     = blockIdx.z;
    const int rbase = blockIdx.y * GBM;
    const int ebase = blockIdx.x * GBN;
    const int tid   = threadIdx.x;
    const int lane  = tid & 31;
    const int wid   = tid >> 5;
    const int wm    = (wid >> 2) * 64;   // warp row offset (2 rows of warps)
    const int wn    = (wid & 3) * 32;    // warp col offset (4 cols of warps)

    // global loaders: thread t -> row t>>1, k-segment (t&1)*16
    const int lrow = tid >> 1;
    const int lseg = (tid & 1) * 16;

    const float* aptr = teacher + ((size_t)(b * VDIM) * PDIM + ref_perm[rbase + lrow]) * DDIM + lseg;
    const int v = 2 * (ebase >> 12) + 1;           // EXTRA_FRAMES {1,3,5,7}
    const int p = (ebase & (PDIM - 1)) + lrow;
    const float* bptr = teacher + ((size_t)(b * VDIM + v) * PDIM + p) * DDIM + lseg;

    float acc[4][4][4];
    #pragma unroll
    for (int i = 0; i < 4; i++)
        #pragma unroll
        for (int j = 0; j < 4; j++)
            #pragma unroll
            for (int k = 0; k < 4; k++) acc[i][j][k] = 0.f;

    uint2 pfa[4], pfb[4];
    float ssq = 0.f;

    // ldmatrix lane addressing
    const int g  = lane >> 3;                 // 0..3
    const int xr = (lane & 7) + (g & 1) * 8;  // row within 16
    const int xk = (g >> 1) * 8;              // k-half select
    uint32_t a_base[4], b_base[2];
    #pragma unroll
    for (int mi = 0; mi < 4; mi++)
        a_base[mi] = (uint32_t)__cvta_generic_to_shared(&As[wm + mi * 16 + xr][xk]);
    #pragma unroll
    for (int nj = 0; nj < 2; nj++)
        b_base[nj] = (uint32_t)__cvta_generic_to_shared(&Bs[wn + nj * 16 + xr][xk]);

    // initial prefetch (kt = 0)
    #pragma unroll
    for (int i = 0; i < 4; i++) {
        float4 xa = *(const float4*)(aptr + i * 4);
        float4 xb = *(const float4*)(bptr + i * 4);
        ssq += xb.x * xb.x + xb.y * xb.y + xb.z * xb.z + xb.w * xb.w;
        __nv_bfloat162 a0, a1, b0, b1;
        a0.x = __float2bfloat16(xa.x); a0.y = __float2bfloat16(xa.y);
        a1.x = __float2bfloat16(xa.z); a1.y = __float2bfloat16(xa.w);
        b0.x = __float2bfloat16(xb.x); b0.y = __float2bfloat16(xb.y);
        b1.x = __float2bfloat16(xb.z); b1.y = __float2bfloat16(xb.w);
        pfa[i] = make_uint2(*(uint32_t*)&a0, *(uint32_t*)&a1);
        pfb[i] = make_uint2(*(uint32_t*)&b0, *(uint32_t*)&b1);
    }

    for (int kt = 0; kt < DDIM; kt += GBK) {
        __syncthreads();
        #pragma unroll
        for (int i = 0; i < 4; i++) {
            *(uint2*)&As[lrow][lseg + i * 4] = pfa[i];
            *(uint2*)&Bs[lrow][lseg + i * 4] = pfb[i];
        }
        __syncthreads();

        if (kt + GBK < DDIM) {
            #pragma unroll
            for (int i = 0; i < 4; i++) {
                float4 xa = *(const float4*)(aptr + kt + GBK + i * 4);
                float4 xb = *(const float4*)(bptr + kt + GBK + i * 4);
                ssq += xb.x * xb.x + xb.y * xb.y + xb.z * xb.z + xb.w * xb.w;
                __nv_bfloat162 a0, a1, b0, b1;
                a0.x = __float2bfloat16(xa.x); a0.y = __float2bfloat16(xa.y);
                a1.x = __float2bfloat16(xa.z); a1.y = __float2bfloat16(xa.w);
                b0.x = __float2bfloat16(xb.x); b0.y = __float2bfloat16(xb.y);
                b1.x = __float2bfloat16(xb.z); b1.y = __float2bfloat16(xb.w);
                pfa[i] = make_uint2(*(uint32_t*)&a0, *(uint32_t*)&a1);
                pfb[i] = make_uint2(*(uint32_t*)&b0, *(uint32_t*)&b1);
            }
        }

        #pragma unroll
        for (int ks = 0; ks < GBK; ks += 16) {
            uint32_t af[4][4], bf[2][4];
            #pragma unroll
            for (int mi = 0; mi < 4; mi++) {
                asm volatile("ldmatrix.sync.aligned.m8n8.x4.shared.b16 {%0,%1,%2,%3}, [%4];"
                    : "=r"(af[mi][0]), "=r"(af[mi][1]), "=r"(af[mi][2]), "=r"(af[mi][3])
                    : "r"(a_base[mi] + ks * 2));
            }
            #pragma unroll
            for (int nj = 0; nj < 2; nj++) {
                asm volatile("ldmatrix.sync.aligned.m8n8.x4.shared.b16 {%0,%1,%2,%3}, [%4];"
                    : "=r"(bf[nj][0]), "=r"(bf[nj][1]), "=r"(bf[nj][2]), "=r"(bf[nj][3])
                    : "r"(b_base[nj] + ks * 2));
            }
            #pragma unroll
            for (int mi = 0; mi < 4; mi++) {
                #pragma unroll
                for (int nj = 0; nj < 4; nj++) {
                    uint32_t bb0 = bf[nj >> 1][nj & 1];
                    uint32_t bb1 = bf[nj >> 1][(nj & 1) + 2];
                    asm volatile(
                        "mma.sync.aligned.m16n8k16.row.col.f32.bf16.bf16.f32 "
                        "{%0,%1,%2,%3}, {%4,%5,%6,%7}, {%8,%9}, {%0,%1,%2,%3};"
                        : "+f"(acc[mi][nj][0]), "+f"(acc[mi][nj][1]),
                          "+f"(acc[mi][nj][2]), "+f"(acc[mi][nj][3])
                        : "r"(af[mi][0]), "r"(af[mi][1]), "r"(af[mi][2]), "r"(af[mi][3]),
                          "r"(bb0), "r"(bb1));
                }
            }
        }
    }

    // finish B-row norms: pair (2r, 2r+1) hold the two halves of row r
    ssq += __shfl_xor_sync(0xffffffffu, ssq, 1);
    if ((tid & 1) == 0) s_inv[lrow] = 1.0f / fmaxf(sqrtf(ssq), 1e-12f);
    __syncthreads();

    // epilogue: scale by inv_norm[e] and write sims
    #pragma unroll
    for (int mi = 0; mi < 4; mi++) {
        #pragma unroll
        for (int nj = 0; nj < 4; nj++) {
            int c0 = wn + nj * 8 + (lane & 3) * 2;
            float iv0 = s_inv[c0], iv1 = s_inv[c0 + 1];
            int r0 = rbase + wm + mi * 16 + (lane >> 2);
            float* out0 = g_sim + ((size_t)(b * NREF + r0)) * EN + ebase + c0;
            float2 w0 = make_float2(acc[mi][nj][0] * iv0, acc[mi][nj][1] * iv1);
            float2 w1 = make_float2(acc[mi][nj][2] * iv0, acc[mi][nj][3] * iv1);
            *(float2*)out0 = w0;
            *(float2*)(out0 + 8 * EN) = w1;
        }
    }
}

// ---------------------------------------------------------------------------
// K2: approximate top-8 candidate indices per (b, r) from bf16 sims
// ---------------------------------------------------------------------------
__device__ __forceinline__ void ins4(float x, int e, float* v, int* id) {
    if (x <= v[3]) return;
    v[3] = x; id[3] = e;
    #pragma unroll
    for (int j = 3; j >= 1; j--) {
        if (v[j] > v[j - 1]) {
            float tv = v[j]; v[j] = v[j - 1]; v[j - 1] = tv;
            int ti = id[j]; id[j] = id[j - 1]; id[j - 1] = ti;
        }
    }
}

__device__ __forceinline__ void ins8(float x, int e, float* v, int* id) {
    if (x <= v[7]) return;
    v[7] = x; id[7] = e;
    #pragma unroll
    for (int j = 7; j >= 1; j--) {
        if (v[j] > v[j - 1]) {
            float tv = v[j]; v[j] = v[j - 1]; v[j - 1] = tv;
            int ti = id[j]; id[j] = id[j - 1]; id[j - 1] = ti;
        }
    }
}

__global__ void k_topk() {
    int r = blockIdx.x, b = blockIdx.y;
    const float* row = g_sim + ((size_t)(b * NREF + r)) * EN;
    int tid = threadIdx.x;

    float v[4] = {-3.4e38f, -3.4e38f, -3.4e38f, -3.4e38f};
    int id[4] = {0, 0, 0, 0};
    for (int e = tid; e < EN; e += 256) ins4(row[e], e, v, id);

    __shared__ float sv[1024];
    __shared__ int   si[1024];
    #pragma unroll
    for (int j = 0; j < 4; j++) { sv[tid * 4 + j] = v[j]; si[tid * 4 + j] = id[j]; }
    __syncthreads();

    if (tid < 32) {
        float v2[4] = {-3.4e38f, -3.4e38f, -3.4e38f, -3.4e38f};
        int id2[4] = {0, 0, 0, 0};
        for (int t = tid * 32; t < tid * 32 + 32; t++) ins4(sv[t], si[t], v2, id2);
        __syncwarp();
        #pragma unroll
        for (int j = 0; j < 4; j++) { sv[tid * 4 + j] = v2[j]; si[tid * 4 + j] = id2[j]; }
        __syncwarp();
        if (tid == 0) {
            float v3[8] = {-3.4e38f, -3.4e38f, -3.4e38f, -3.4e38f,
                           -3.4e38f, -3.4e38f, -3.4e38f, -3.4e38f};
            int id3[8] = {0, 0, 0, 0, 0, 0, 0, 0};
            for (int t = 0; t < 128; t++) ins8(sv[t], si[t], v3, id3);
            #pragma unroll
            for (int j = 0; j < 8; j++) g_cand[(b * NREF + r) * NCAND + j] = id3[j];
        }
    }
}

// ---------------------------------------------------------------------------
// K3: exact fp32 re-rank of the 8 candidates -> exact top-4 indices
// ---------------------------------------------------------------------------
__global__ void k_rerank(const float* __restrict__ teacher,
                         const int* __restrict__ ref_perm) {
    int r = blockIdx.x, b = blockIdx.y;
    int tid = threadIdx.x, w = tid >> 5, lane = tid & 31;

    if (r == 0 && b == 0 && tid < 3) g_accum[tid] = 0.f;

    int e = g_cand[(b * NREF + r) * NCAND + w];
    int v = 2 * (e >> 12) + 1, p = e & (PDIM - 1);
    const float* er = teacher + ((size_t)(b * VDIM + v) * PDIM + p) * DDIM;
    const float* rr = teacher + ((size_t)(b * VDIM) * PDIM + ref_perm[r]) * DDIM;

    float dot = 0.f, ss = 0.f;
    #pragma unroll
    for (int j = 0; j < 8; j++) {
        int idx = lane * 4 + j * 128;
        float4 x = *(const float4*)(er + idx);
        float4 y = *(const float4*)(rr + idx);
        dot += x.x * y.x + x.y * y.y + x.z * y.z + x.w * y.w;
        ss  += x.x * x.x + x.y * x.y + x.z * x.z + x.w * x.w;
    }
    #pragma unroll
    for (int o = 16; o; o >>= 1) {
        dot += __shfl_xor_sync(0xffffffffu, dot, o);
        ss  += __shfl_xor_sync(0xffffffffu, ss, o);
    }

    __shared__ float s_sim[NCAND];
    __shared__ int   s_e[NCAND];
    if (lane == 0) {
        s_sim[w] = dot / fmaxf(sqrtf(ss), 1e-12f);
        s_e[w] = e;
    }
    __syncthreads();

    if (tid == 0) {
        // exact top-4 of 8; ties broken by smaller index (jax.lax.top_k order)
        bool used[NCAND] = {false, false, false, false, false, false, false, false};
        #pragma unroll
        for (int j = 0; j < 4; j++) {
            int best = -1;
            float bv = -3.4e38f; int be = 0x7fffffff;
            for (int t = 0; t < NCAND; t++) {
                if (used[t]) continue;
                if (s_sim[t] > bv || (s_sim[t] == bv && s_e[t] < be)) {
                    bv = s_sim[t]; be = s_e[t]; best = t;
                }
            }
            used[best] = true;
            g_topk[(b * NREF + r) * 4 + j] = s_e[best];
        }
    }
}

// ---------------------------------------------------------------------------
// K4: KL + smooth-L1 losses. One warp per KL row-pair.
//   warps [0,1536):      d1   (3 iters x B x 256)
//   warps [1536,3584):   d2   (B x 256 x 4)  -- computed once (identical per iter)
//   warps [3584,9728):   d3   (3 iters x B x 256 x 4)
// ---------------------------------------------------------------------------
__global__ void __launch_bounds__(256)
k_loss(const float* __restrict__ teacher, const float* __restrict__ student,
       const int* __restrict__ ref_perm, const int* __restrict__ shared_perm) {
    __shared__ float sacc[3];
    int tid = threadIdx.x;
    if (tid < 3) sacc[tid] = 0.f;
    __syncthreads();

    int w = blockIdx.x * 8 + (tid >> 5);
    int lane = tid & 31;

    const float *pa, *pb, *pc, *pd;
    int target;
    if (w < 1536) {
        target = 0;
        int i = w / 512, rem = w & 511;
        int b = rem >> 8, r = rem & 255;
        int rp = ref_perm[r], sp = shared_perm[r];
        pa = teacher + ((size_t)(b * VDIM) * PDIM + rp) * DDIM;
        pb = teacher + ((size_t)(b * VDIM + c_ST[i]) * PDIM + sp) * DDIM;
        pc = student + ((size_t)(b * 4) * PDIM + rp) * DDIM;
        pd = student + ((size_t)(b * 4 + c_SS[i]) * PDIM + sp) * DDIM;
    } else if (w < 3584) {
        target = 1;
        int t = w - 1536;
        int b = t >> 10, rem = t & 1023;
        int r = rem >> 2, k = rem & 3;
        int rp = ref_perm[r];
        int e = g_topk[((b << 8) + r) * 4 + k];
        int v = 2 * (e >> 12) + 1, p = e & (PDIM - 1);
        pa = teacher + ((size_t)(b * VDIM) * PDIM + rp) * DDIM;
        pc = student + ((size_t)(b * 4) * PDIM + rp) * DDIM;
        pb = pd = teacher + ((size_t)(b * VDIM + v) * PDIM + p) * DDIM;
    } else {
        target = 2;
        int t = w - 3584;
        int i = t >> 11, rem = t & 2047;
        int b = rem >> 10, r = (rem >> 2) & 255, k = rem & 3;
        int sp = shared_perm[r];
        int e = g_topk[((b << 8) + r) * 4 + k];
        int v = 2 * (e >> 12) + 1, p = e & (PDIM - 1);
        pa = teacher + ((size_t)(b * VDIM + c_ST[i]) * PDIM + sp) * DDIM;
        pc = student + ((size_t)(b * 4 + c_SS[i]) * PDIM + sp) * DDIM;
        pb = pd = teacher + ((size_t)(b * VDIM + v) * PDIM + p) * DDIM;
    }

    float dt[32], ds[32];
    bool same = (pb == pd);
    #pragma unroll
    for (int j = 0; j < 8; j++) {
        int idx = lane * 4 + j * 128;
        float4 A  = *(const float4*)(pa + idx);
        float4 Bv = *(const float4*)(pb + idx);
        float4 C  = *(const float4*)(pc + idx);
        float4 Dv = same ? Bv : *(const float4*)(pd + idx);
        dt[4 * j + 0] = A.x - Bv.x; dt[4 * j + 1] = A.y - Bv.y;
        dt[4 * j + 2] = A.z - Bv.z; dt[4 * j + 3] = A.w - Bv.w;
        ds[4 * j + 0] = C.x - Dv.x; ds[4 * j + 1] = C.y - Dv.y;
        ds[4 * j + 2] = C.z - Dv.z; ds[4 * j + 3] = C.w - Dv.w;
    }

    float mt = -3.4e38f, ms = -3.4e38f;
    #pragma unroll
    for (int i = 0; i < 32; i++) { mt = fmaxf(mt, dt[i]); ms = fmaxf(ms, ds[i]); }
    #pragma unroll
    for (int o = 16; o; o >>= 1) {
        mt = fmaxf(mt, __shfl_xor_sync(0xffffffffu, mt, o));
        ms = fmaxf(ms, __shfl_xor_sync(0xffffffffu, ms, o));
    }
    float st = 0.f, ssum = 0.f;
    #pragma unroll
    for (int i = 0; i < 32; i++) { st += expf(dt[i] - mt); ssum += expf(ds[i] - ms); }
    #pragma unroll
    for (int o = 16; o; o >>= 1) {
        st   += __shfl_xor_sync(0xffffffffu, st, o);
        ssum += __shfl_xor_sync(0xffffffffu, ssum, o);
    }
    float lset = mt + logf(st);
    float lses = ms + logf(ssum);

    float acc = 0.f;
    #pragma unroll
    for (int i = 0; i < 32; i++) acc += expf(dt[i] - lset) * (dt[i] - ds[i]);
    #pragma unroll
    for (int o = 16; o; o >>= 1) acc += __shfl_xor_sync(0xffffffffu, acc, o);

    if (lane == 0) {
        float kl = acc - lset + lses;
        float ax = fabsf(kl);
        float sl = (ax < 0.5f) ? kl * kl : (ax - 0.25f);   // smooth_l1, beta=0.5
        atomicAdd(&sacc[target], sl);
    }
    __syncthreads();
    if (tid < 3) atomicAdd(&g_accum[tid], sacc[tid]);
}

// ---------------------------------------------------------------------------
// K5: final combine
//   loss = sum_d1/1536 + sum_d2/2048 + sum_d3/6144
// ---------------------------------------------------------------------------
__global__ void k_final(float* __restrict__ out) {
    out[0] = g_accum[0] * (1.0f / 1536.0f)
           + g_accum[1] * (1.0f / 2048.0f)
           + g_accum[2] * (1.0f / 6144.0f);
}

// ---------------------------------------------------------------------------
extern "C" void kernel_launch(void* const* d_in, const int* in_sizes, int n_in,
                              void* d_out, int out_size) {
    const float* teacher     = (const float*)d_in[0];
    const float* student     = (const float*)d_in[1];
    const int*   ref_perm    = (const int*)d_in[2];
    const int*   shared_perm = (const int*)d_in[3];
    float* out = (float*)d_out;

    k_gemm<<<dim3(EN / GBN, NREF / GBM, BDIM), 256>>>(teacher, ref_perm);
    k_topk<<<dim3(NREF, BDIM), 256>>>();
    k_rerank<<<dim3(NREF, BDIM), 256>>>(teacher, ref_perm);
    k_loss<<<9728 / 8, 256>>>(teacher, student, ref_perm, shared_perm);
    k_final<<<1, 1>>>(out);
}